// round 12
// baseline (speedup 1.0000x reference)
#include <cuda_runtime.h>
#include <math.h>

#define NUM_BINS 36
#define WARPS_PER_BLOCK 4
#define PATCH 32
#define HBINS 38                   // 36 + 2 overflow bins (36->0, 37->1)
#define HSLOT (HBINS * 32)         // 1216 floats: hist[38][32]
#define WSTRIDE 1296               // hist + raw(40) + smoothed(40)

// Discrete Gaussian smoothing kernel (sigma=1.6, ksize=5), analytically:
// k_j = I_|j|(2.56) / (I_0 + 2 I_1 + 2 I_2)   (the e^{-t} factor cancels).
#define SK0 0.11906250f
#define SK1 0.23112358f
#define SK2 0.29962786f

// Gaussian weights g[r] = exp(-(r-15.5)^2 * 36/2048), r = 0..31 (analytic).
#define GSUMF 13.3331107f
__host__ __device__ constexpr float GWv(int r) {
    constexpr float t[16] = {
        0.01465249f, 0.02482757f, 0.04061518f, 0.06414674f,
        0.09781210f, 0.14399383f, 0.20465581f, 0.28082614f,
        0.37203420f, 0.47583903f, 0.58758270f, 0.70050263f,
        0.80627370f, 0.89595700f, 0.96122114f, 0.99561511f };
    return (r < 16) ? t[r] : t[31 - r];
}

typedef unsigned long long u64;

// Packed f32x2 ops (sm_103a FFMA2/FADD2/FMUL2 — only reachable via PTX).
#define FMA2(d, a, b, c) asm("fma.rn.f32x2 %0, %1, %2, %3;" : "=l"(d) : "l"(a), "l"(b), "l"(c))
#define MUL2(d, a, b)    asm("mul.rn.f32x2 %0, %1, %2;"     : "=l"(d) : "l"(a), "l"(b))
#define ADD2(d, a, b)    asm("add.rn.f32x2 %0, %1, %2;"     : "=l"(d) : "l"(a), "l"(b))
#define SUB2(d, a, b)    asm("sub.rn.f32x2 %0, %1, %2;"     : "=l"(d) : "l"(a), "l"(b))
#define UPK2(l0, h0, s)  asm("mov.b64 {%0, %1}, %2;"        : "=f"(l0), "=f"(h0) : "l"(s))
#define UPKI2(l0, h0, s) asm("mov.b64 {%0, %1}, %2;"        : "=r"(l0), "=r"(h0) : "l"(s))

__device__ __forceinline__ u64 pack2(float a, float b) {
    u64 r; asm("mov.b64 %0, {%1, %2};" : "=l"(r) : "f"(a), "f"(b)); return r;
}

__device__ __forceinline__ float sqrt_approx(float x) {
    float r; asm("sqrt.approx.f32 %0, %1;" : "=f"(r) : "f"(x)); return r;
}

// ---------------------------------------------------------------------------
// One warp per patch. Two rows per iteration, all packable math in f32x2.
// Conv-order swap: shuffle the RAW pixel row once, horizontal combos in-reg,
// vertical taps via rolling window. Bin index via two-step magic-float:
//   V2 = v + 53.5 (representable), M = V2 + 2^23 -> mantissa = floor(v+54).
// ---------------------------------------------------------------------------
__global__ void __launch_bounds__(WARPS_PER_BLOCK * 32, 9)
patch_orient_kernel(const float* __restrict__ in, float* __restrict__ out) {
    __shared__ __align__(16) float hist[WARPS_PER_BLOCK * WSTRIDE];

    const unsigned FULL = 0xffffffffu;
    int tid  = threadIdx.x;
    int warp = tid >> 5;
    int lane = tid & 31;
    int patch = blockIdx.x * WARPS_PER_BLOCK + warp;

    // Per-lane column weight factor, fully folded:
    // kk = g_lane * 0.125 / GSUM^2  (row literal g_r multiplies in-loop).
    float xg = (float)lane - 15.5f;
    float g  = expf(-xg * xg * 0.017578125f);
    const float kkf = g * (0.125f / (GSUMF * GSUMF));
    const u64 CKK = pack2(kkf, kkf);

    // Packed constants (register pairs; FFMA2 cannot read cbank).
    // Poly coefficients: ~1ulp atan minimax PRE-SCALED by 18/pi.
    const u64 CEPS8 = pack2(8e-8f, 8e-8f);
    const u64 CEPS2 = pack2(6.4e-7f, 6.4e-7f);
    const u64 CK  = pack2(5.7295779513082321f, 5.7295779513082321f); // 18/pi
    const u64 CC7 = pack2( 0.0161782457f,  0.0161782457f);
    const u64 CC6 = pack2(-0.0914263090f, -0.0914263090f);
    const u64 CC5 = pack2( 0.2435356455f,  0.2435356455f);
    const u64 CC4 = pack2(-0.4290686200f, -0.4290686200f);
    const u64 CC3 = pack2( 0.6093287740f,  0.6093287740f);
    const u64 CC2 = pack2(-0.8137568480f, -0.8137568480f);
    const u64 CC1 = pack2( 1.1454970880f,  1.1454970880f);
    const u64 CC0 = pack2(-1.9098460550f, -1.9098460550f);
    // Two-step magic binning (all constants exactly representable):
    //   V2 = v + 53.5;  M = V2 + 2^23  -> mantissa low bits = floor(v+54).
    //   FO = M - (2^23 + 54) = floor(v) exactly (integer diff in [-18,18]).
    const u64 C53  = pack2(53.5f, 53.5f);
    const u64 CMAG = pack2(8388608.0f, 8388608.0f);      // 2^23
    const u64 CMOF = pack2(8388662.0f, 8388662.0f);      // 2^23 + 54

    float* h = hist + warp * WSTRIDE;
#pragma unroll
    for (int b = 0; b < HBINS / 2; b++)                   // packed zero-init
        *(u64*)(h + b * 64 + lane * 2) = 0ull;
    __syncwarp();   // init writes cross lane columns -> publish first

    const float* src = in + (size_t)patch * (PATCH * PATCH) + lane;
    float p[PATCH];
#pragma unroll
    for (int r = 0; r < 6; r++) p[r] = src[r * PATCH];   // prefetch prologue

    // Base pointer pre-biased by -36 rows so addr = base + i0raw*128.
    float* hl = h + lane - 36 * 32;

    const int lm1 = (lane == 0) ? 0 : lane - 1;
    const int lp1 = (lane == 31) ? 31 : lane + 1;

    // Rolling window: CARR = (hd/hs of rows r0-1, r0). Row -1 clamps to row 0.
    float pl0 = __shfl_sync(FULL, p[0], lm1);
    float pr0 = __shfl_sync(FULL, p[0], lp1);
    float hd0 = pr0 - pl0;
    float hs0 = fmaf(2.0f, p[0], pl0 + pr0);
    u64 CARR_HD = pack2(hd0, hd0);
    u64 CARR_HS = pack2(hs0, hs0);

#pragma unroll
    for (int i = 0; i < PATCH / 2; i++) {
        const int r0 = 2 * i, r1 = 2 * i + 1;
        const int f1 = (r1 + 1 < PATCH) ? r1 + 1 : PATCH - 1;  // row 32 -> 31

        // Fresh rows (r1, f1): ONE packed pixel shuffle pair.
        u64 P  = pack2(p[r1], p[f1]);
        u64 PL = __shfl_sync(FULL, P, lm1);
        u64 PR = __shfl_sync(FULL, P, lp1);

        // Prefetch ring: rows r0+6, r0+7 (guards are compile-time).
        if (r0 + 6 < PATCH) p[r0 + 6] = src[(r0 + 6) * PATCH];
        if (r0 + 7 < PATCH) p[r0 + 7] = src[(r0 + 7) * PATCH];

        u64 FHD; SUB2(FHD, PR, PL);              // (hd[r1], hd[r1+1])
        u64 TT;  ADD2(TT, PL, PR);
        u64 PP2; ADD2(PP2, P, P);
        u64 FHS; ADD2(FHS, TT, PP2);             // (hs[r1], hs[r1+1])

        // GX = CARR_HD + 2*MID + FHD, MID = (hd[r0], hd[r1]).
        float chd_lo, chd_hi; UPK2(chd_lo, chd_hi, CARR_HD);
        float fhd_lo, fhd_hi; UPK2(fhd_lo, fhd_hi, FHD);
        u64 MID = pack2(chd_hi, fhd_lo);
        u64 TG;  ADD2(TG, CARR_HD, FHD);
        u64 MID2; ADD2(MID2, MID, MID);
        u64 GX;  ADD2(GX, TG, MID2);             // 8*gx rows (r0, r1)
        u64 GXE; ADD2(GXE, GX, CEPS8);           // + 8e-8 (ref eps, scaled)
        u64 GY;  SUB2(GY, FHS, CARR_HS);         // 8*gy = hs[r+1]-hs[r-1]
        CARR_HD = FHD;
        CARR_HS = FHS;

        u64 M2;  FMA2(M2, GY, GY, CEPS2);
        FMA2(M2, GXE, GXE, M2);

        float m20, m21; UPK2(m20, m21, M2);
        float q0 = sqrt_approx(m20);
        float q1 = sqrt_approx(m21);
        u64 GP = pack2(GWv(r0), GWv(r1));        // row weights: literals
        u64 WW;  MUL2(WW, GP, CKK);
        u64 SQ = pack2(q0, q1);
        u64 MAG; MUL2(MAG, SQ, WW);

        float gx0, gx1, gy0, gy1;
        UPK2(gx0, gx1, GXE);
        UPK2(gy0, gy1, GY);

        // atan2 front (scalar: MUFU + min/max with |.| operand modifiers).
        float mx0 = fmaxf(fabsf(gx0), fabsf(gy0));
        float mn0 = fminf(fabsf(gx0), fabsf(gy0));
        float t0  = __fdividef(mn0, mx0);
        float mx1 = fmaxf(fabsf(gx1), fabsf(gy1));
        float mn1 = fminf(fabsf(gx1), fabsf(gy1));
        float t1  = __fdividef(mn1, mx1);

        // Packed pre-scaled atan poly: u = (18/pi)*atan(t), u in [0, 4.5].
        u64 T = pack2(t0, t1);
        u64 S;  MUL2(S, T, T);
        u64 Q;  FMA2(Q, CC7, S, CC6);
        FMA2(Q, Q, S, CC5);
        FMA2(Q, Q, S, CC4);
        FMA2(Q, Q, S, CC3);
        FMA2(Q, Q, S, CC2);
        FMA2(Q, Q, S, CC1);
        FMA2(Q, Q, S, CC0);
        FMA2(Q, Q, S, CK);                       // Q = 18/pi + s*P(s)
        u64 U;  MUL2(U, Q, T);                   // u = Q*t
        float u0, u1; UPK2(u0, u1, U);

        // Octant fixups in bin units (pi/2 -> 9, pi -> 18). u stays in [0,18].
        if (fabsf(gy0) > fabsf(gx0)) u0 = 9.0f  - u0;
        if (gx0 < 0.0f)              u0 = 18.0f - u0;
        float v0 = copysignf(u0, gy0);
        if (fabsf(gy1) > fabsf(gx1)) u1 = 9.0f  - u1;
        if (gx1 < 0.0f)              u1 = 18.0f - u1;
        float v1 = copysignf(u1, gy1);

        // Packed two-step magic binning. k = floor(v+54) in [36,72];
        // ties at the range ends resolve to even = in-range (36/72).
        u64 V = pack2(v0, v1);
        u64 V2;  ADD2(V2, V, C53);               // v + 53.5 (representable)
        u64 M;   ADD2(M, V2, CMAG);              // + 2^23: mantissa = k
        u64 FO;  SUB2(FO, M, CMOF);              // k - 54, exact
        u64 WO1; SUB2(WO1, V, FO);               // frac (may be 0/1 at ties)
        u64 W1;  MUL2(W1, WO1, MAG);
        u64 W0;  SUB2(W0, MAG, W1);

        unsigned mlo, mhi; UPKI2(mlo, mhi, M);
        int i00 = mlo & 0x7FFFFF;               // k0 in [36, 72]
        int i01 = mhi & 0x7FFFFF;               // k1 in [36, 72]
        float w0v0, w0v1; UPK2(w0v0, w0v1, W0);
        float w1v0, w1v1; UPK2(w1v0, w1v1, W1);

        float* q0p = hl + i00 * 32;             // bank == lane: conflict-free
        q0p[0]  += w0v0;
        q0p[32] += w1v0;
        float* q1p = hl + i01 * 32;
        q1p[0]  += w0v1;
        q1p[32] += w1v1;
    }
    __syncwarp();

    // Packed reduce: 38 bins x 32 lane-slots as 16 u64 per bin, lane-rotated.
    // Lane l sums bin l; lanes 0-5 also bins 32+l.
    u64 ACC = 0ull;
#pragma unroll
    for (int k = 0; k < 16; k++) {
        int kk = ((k + lane) & 15) * 2;          // rotate -> spread banks
        u64 v = *(const u64*)(h + lane * 32 + kk);
        ADD2(ACC, ACC, v);
    }
    float aLo, aHi; UPK2(aLo, aHi, ACC);
    float acc = aLo + aHi;

    float acc2 = 0.0f;
    if (lane < 6) {
        u64 ACC2 = 0ull;
#pragma unroll
        for (int k = 0; k < 16; k++) {
            int kk = ((k + lane) & 15) * 2;
            u64 v = *(const u64*)(h + (32 + lane) * 32 + kk);
            ADD2(ACC2, ACC2, v);
        }
        float bLo, bHi; UPK2(bLo, bHi, ACC2);
        acc2 = bLo + bHi;
    }
    // Fold overflow bins: 36 -> 0, 37 -> 1 (held by lanes 4, 5 in acc2).
    float b36 = __shfl_sync(FULL, acc2, 4);
    float b37 = __shfl_sync(FULL, acc2, 5);
    if (lane == 0) acc += b36;
    if (lane == 1) acc += b37;

    float* red  = h + HSLOT;        // 36 raw bins
    float* red2 = red + 40;         // 36 smoothed bins
    red[lane] = acc;
    if (lane < 4) red[32 + lane] = acc2;
    __syncwarp();

    // Smooth all 36 bins with wrap-padded 5-tap kernel (immediate coefficients).
    float sv = SK0 * red[(lane + 34) % 36];
    sv = fmaf(SK1, red[(lane + 35) % 36], sv);
    sv = fmaf(SK2, red[lane],            sv);
    sv = fmaf(SK1, red[(lane + 1) % 36], sv);
    sv = fmaf(SK0, red[(lane + 2) % 36], sv);
    red2[lane] = sv;
    float sv2 = -1e30f;
    if (lane < 4) {
        int b = 32 + lane;
        sv2 = SK0 * red[(b + 34) % 36];
        sv2 = fmaf(SK1, red[(b + 35) % 36], sv2);
        sv2 = fmaf(SK2, red[b],             sv2);
        sv2 = fmaf(SK1, red[(b + 1) % 36],  sv2);
        sv2 = fmaf(SK0, red[(b + 2) % 36],  sv2);
        red2[b] = sv2;
    }
    __syncwarp();

    // Per-lane candidate: bin `lane`, optionally replaced by bin `32+lane`
    // (strict > keeps lowest-index-wins tie semantics since 32+lane > lane).
    float v = sv;
    int idx = lane;
    if (lane < 4 && sv2 > v) { v = sv2; idx = 32 + lane; }

    // Warp argmax (lowest index on ties, matching jnp.argmax).
#pragma unroll
    for (int off = 16; off; off >>= 1) {
        float v2 = __shfl_xor_sync(FULL, v, off);
        int   i2 = __shfl_xor_sync(FULL, idx, off);
        if (v2 > v || (v2 == v && i2 < idx)) { v = v2; idx = i2; }
    }

    if (lane == 0) {
        float left  = red2[(idx + 35) % 36];
        float right = red2[(idx + 1) % 36];
        float denom = left + right - 2.0f * v;
        float c = 0.5f * (left - right) / denom;
        // angle = pi - (idx + c) * 2*pi/36   (the /HW scale cancels everywhere)
        float angle = 3.14159265358979f - ((float)idx + c) * 0.17453292519943295f;
        out[patch] = angle;
    }
}

// ---------------------------------------------------------------------------
extern "C" void kernel_launch(void* const* d_in, const int* in_sizes, int n_in,
                              void* d_out, int out_size) {
    const float* patch = (const float*)d_in[0];
    float* out = (float*)d_out;
    int n_patches = in_sizes[0] / (PATCH * PATCH);   // 32768

    int blocks = n_patches / WARPS_PER_BLOCK;        // 8192
    patch_orient_kernel<<<blocks, WARPS_PER_BLOCK * 32>>>(patch, out);
}

// round 13
// speedup vs baseline: 1.0161x; 1.0161x over previous
#include <cuda_runtime.h>
#include <math.h>

#define NUM_BINS 36
#define WARPS_PER_BLOCK 4
#define PATCH 32
#define HBINS 38                   // 36 + 2 overflow bins (36->0, 37->1)
#define HSLOT (HBINS * 32)         // 1216 floats: hist[38][32]
#define WSTRIDE 1296               // hist + raw(40) + smoothed(40)

// Discrete Gaussian smoothing kernel (sigma=1.6, ksize=5), analytically:
// k_j = I_|j|(2.56) / (I_0 + 2 I_1 + 2 I_2)   (the e^{-t} factor cancels).
#define SK0 0.11906250f
#define SK1 0.23112358f
#define SK2 0.29962786f

// Gaussian weights g[r] = exp(-(r-15.5)^2 * 36/2048), r = 0..31 (analytic).
#define GSUMF 13.3331107f
__host__ __device__ constexpr float GWv(int r) {
    constexpr float t[16] = {
        0.01465249f, 0.02482757f, 0.04061518f, 0.06414674f,
        0.09781210f, 0.14399383f, 0.20465581f, 0.28082614f,
        0.37203420f, 0.47583903f, 0.58758270f, 0.70050263f,
        0.80627370f, 0.89595700f, 0.96122114f, 0.99561511f };
    return (r < 16) ? t[r] : t[31 - r];
}

typedef unsigned long long u64;

// Packed f32x2 ops (sm_103a FFMA2/FADD2/FMUL2 — only reachable via PTX).
#define FMA2(d, a, b, c) asm("fma.rn.f32x2 %0, %1, %2, %3;" : "=l"(d) : "l"(a), "l"(b), "l"(c))
#define MUL2(d, a, b)    asm("mul.rn.f32x2 %0, %1, %2;"     : "=l"(d) : "l"(a), "l"(b))
#define ADD2(d, a, b)    asm("add.rn.f32x2 %0, %1, %2;"     : "=l"(d) : "l"(a), "l"(b))
#define SUB2(d, a, b)    asm("sub.rn.f32x2 %0, %1, %2;"     : "=l"(d) : "l"(a), "l"(b))
#define UPK2(l0, h0, s)  asm("mov.b64 {%0, %1}, %2;"        : "=f"(l0), "=f"(h0) : "l"(s))

__device__ __forceinline__ u64 pack2(float a, float b) {
    u64 r; asm("mov.b64 %0, {%1, %2};" : "=l"(r) : "f"(a), "f"(b)); return r;
}

__device__ __forceinline__ float sqrt_approx(float x) {
    float r; asm("sqrt.approx.f32 %0, %1;" : "=f"(r) : "f"(x)); return r;
}

// ---------------------------------------------------------------------------
// One warp per patch. Two rows per iteration, all packable math in f32x2.
// Conv-order swap: shuffle the RAW pixel row once, horizontal combos in-reg,
// vertical taps via rolling window. Scalar tail (floor/F2I) — proven fastest.
// Magnitude path scalar with FMUL-immediate row-weight literals.
// ---------------------------------------------------------------------------
__global__ void __launch_bounds__(WARPS_PER_BLOCK * 32, 9)
patch_orient_kernel(const float* __restrict__ in, float* __restrict__ out) {
    __shared__ __align__(16) float hist[WARPS_PER_BLOCK * WSTRIDE];

    const unsigned FULL = 0xffffffffu;
    int tid  = threadIdx.x;
    int warp = tid >> 5;
    int lane = tid & 31;
    int patch = blockIdx.x * WARPS_PER_BLOCK + warp;

    // Per-lane column weight factor, fully folded:
    // kk = g_lane * 0.125 / GSUM^2  (row literal g_r multiplies in the loop).
    float xg = (float)lane - 15.5f;
    float g  = expf(-xg * xg * 0.017578125f);
    const float kkf = g * (0.125f / (GSUMF * GSUMF));

    // Packed constants (register pairs; FFMA2 cannot read cbank).
    // Poly coefficients: ~1ulp atan minimax PRE-SCALED by 18/pi.
    const u64 CEPS8 = pack2(8e-8f, 8e-8f);
    const u64 CEPS2 = pack2(6.4e-7f, 6.4e-7f);
    const u64 CK  = pack2(5.7295779513082321f, 5.7295779513082321f); // 18/pi
    const u64 CC7 = pack2( 0.0161782457f,  0.0161782457f);
    const u64 CC6 = pack2(-0.0914263090f, -0.0914263090f);
    const u64 CC5 = pack2( 0.2435356455f,  0.2435356455f);
    const u64 CC4 = pack2(-0.4290686200f, -0.4290686200f);
    const u64 CC3 = pack2( 0.6093287740f,  0.6093287740f);
    const u64 CC2 = pack2(-0.8137568480f, -0.8137568480f);
    const u64 CC1 = pack2( 1.1454970880f,  1.1454970880f);
    const u64 CC0 = pack2(-1.9098460550f, -1.9098460550f);

    float* h = hist + warp * WSTRIDE;
#pragma unroll
    for (int b = 0; b < HBINS / 2; b++)                   // packed zero-init
        *(u64*)(h + b * 64 + lane * 2) = 0ull;
    __syncwarp();   // init writes cross lane columns -> publish first

    const float* src = in + (size_t)patch * (PATCH * PATCH) + lane;
    float p[PATCH];
#pragma unroll
    for (int r = 0; r < 6; r++) p[r] = src[r * PATCH];   // prefetch prologue

    // Base pointer pre-biased by -36 rows so addr = base + i0raw*128.
    float* hl = h + lane - 36 * 32;

    const int lm1 = (lane == 0) ? 0 : lane - 1;
    const int lp1 = (lane == 31) ? 31 : lane + 1;

    // Rolling window: CARR = (hd/hs of rows r0-1, r0). Row -1 clamps to row 0.
    float pl0 = __shfl_sync(FULL, p[0], lm1);
    float pr0 = __shfl_sync(FULL, p[0], lp1);
    float hd0 = pr0 - pl0;
    float hs0 = fmaf(2.0f, p[0], pl0 + pr0);
    u64 CARR_HD = pack2(hd0, hd0);
    u64 CARR_HS = pack2(hs0, hs0);

#pragma unroll
    for (int i = 0; i < PATCH / 2; i++) {
        const int r0 = 2 * i, r1 = 2 * i + 1;
        const int f1 = (r1 + 1 < PATCH) ? r1 + 1 : PATCH - 1;  // row 32 -> 31

        // Fresh rows (r1, f1): ONE packed pixel shuffle pair.
        u64 P  = pack2(p[r1], p[f1]);
        u64 PL = __shfl_sync(FULL, P, lm1);
        u64 PR = __shfl_sync(FULL, P, lp1);

        // Prefetch ring: rows r0+6, r0+7 (guards are compile-time).
        if (r0 + 6 < PATCH) p[r0 + 6] = src[(r0 + 6) * PATCH];
        if (r0 + 7 < PATCH) p[r0 + 7] = src[(r0 + 7) * PATCH];

        u64 FHD; SUB2(FHD, PR, PL);              // (hd[r1], hd[r1+1])
        u64 TT;  ADD2(TT, PL, PR);
        u64 PP2; ADD2(PP2, P, P);
        u64 FHS; ADD2(FHS, TT, PP2);             // (hs[r1], hs[r1+1])

        // GX = CARR_HD + 2*MID + FHD, MID = (hd[r0], hd[r1]).
        float chd_lo, chd_hi; UPK2(chd_lo, chd_hi, CARR_HD);
        float fhd_lo, fhd_hi; UPK2(fhd_lo, fhd_hi, FHD);
        u64 MID = pack2(chd_hi, fhd_lo);
        u64 TG;  ADD2(TG, CARR_HD, FHD);
        u64 MID2; ADD2(MID2, MID, MID);
        u64 GX;  ADD2(GX, TG, MID2);             // 8*gx rows (r0, r1)
        u64 GXE; ADD2(GXE, GX, CEPS8);           // + 8e-8 (ref eps, scaled)
        u64 GY;  SUB2(GY, FHS, CARR_HS);         // 8*gy = hs[r+1]-hs[r-1]
        CARR_HD = FHD;
        CARR_HS = FHS;

        u64 M2;  FMA2(M2, GY, GY, CEPS2);
        FMA2(M2, GXE, GXE, M2);

        // Scalar magnitude path: FMUL + FMUL-immediate (row weight literal).
        float m20, m21; UPK2(m20, m21, M2);
        float mag0 = (sqrt_approx(m20) * kkf) * GWv(r0);
        float mag1 = (sqrt_approx(m21) * kkf) * GWv(r1);

        float gx0, gx1, gy0, gy1;
        UPK2(gx0, gx1, GXE);
        UPK2(gy0, gy1, GY);

        // atan2 front (scalar: MUFU + min/max with |.| operand modifiers).
        float mx0 = fmaxf(fabsf(gx0), fabsf(gy0));
        float mn0 = fminf(fabsf(gx0), fabsf(gy0));
        float t0  = __fdividef(mn0, mx0);
        float mx1 = fmaxf(fabsf(gx1), fabsf(gy1));
        float mn1 = fminf(fabsf(gx1), fabsf(gy1));
        float t1  = __fdividef(mn1, mx1);

        // Packed pre-scaled atan poly: u = (18/pi)*atan(t), u in [0, 4.5].
        u64 T = pack2(t0, t1);
        u64 S;  MUL2(S, T, T);
        u64 Q;  FMA2(Q, CC7, S, CC6);
        FMA2(Q, Q, S, CC5);
        FMA2(Q, Q, S, CC4);
        FMA2(Q, Q, S, CC3);
        FMA2(Q, Q, S, CC2);
        FMA2(Q, Q, S, CC1);
        FMA2(Q, Q, S, CC0);
        FMA2(Q, Q, S, CK);                       // Q = 18/pi + s*P(s)
        u64 U;  MUL2(U, Q, T);                   // u = Q*t
        float u0, u1; UPK2(u0, u1, U);

        // Octant fixups in bin units (pi/2 -> 9, pi -> 18). u stays in [0,18].
        if (fabsf(gy0) > fabsf(gx0)) u0 = 9.0f  - u0;
        if (gx0 < 0.0f)              u0 = 18.0f - u0;
        float v0 = copysignf(u0, gy0);
        if (fabsf(gy1) > fabsf(gx1)) u1 = 9.0f  - u1;
        if (gx1 < 0.0f)              u1 = 18.0f - u1;
        float v1 = copysignf(u1, gy1);

        // o = v + 54 is in [36, 72] by construction (no guard needed).
        float o0 = v0 + 54.0f;
        float fo0 = floorf(o0);
        float wo10 = o0 - fo0;
        int i00 = (int)fo0;                     // in [36, 72]
        float w1v0 = wo10 * mag0;
        float w0v0 = mag0 - w1v0;
        float* q0p = hl + i00 * 32;             // bank == lane: conflict-free
        q0p[0]  += w0v0;
        q0p[32] += w1v0;

        float o1 = v1 + 54.0f;
        float fo1 = floorf(o1);
        float wo11 = o1 - fo1;
        int i01 = (int)fo1;
        float w1v1 = wo11 * mag1;
        float w0v1 = mag1 - w1v1;
        float* q1p = hl + i01 * 32;
        q1p[0]  += w0v1;
        q1p[32] += w1v1;
    }
    __syncwarp();

    // Packed reduce: 38 bins x 32 lane-slots as 16 u64 per bin, lane-rotated.
    // Lane l sums bin l; lanes 0-5 also bins 32+l.
    u64 ACC = 0ull;
#pragma unroll
    for (int k = 0; k < 16; k++) {
        int kk = ((k + lane) & 15) * 2;          // rotate -> spread banks
        u64 v = *(const u64*)(h + lane * 32 + kk);
        ADD2(ACC, ACC, v);
    }
    float aLo, aHi; UPK2(aLo, aHi, ACC);
    float acc = aLo + aHi;

    float acc2 = 0.0f;
    if (lane < 6) {
        u64 ACC2 = 0ull;
#pragma unroll
        for (int k = 0; k < 16; k++) {
            int kk = ((k + lane) & 15) * 2;
            u64 v = *(const u64*)(h + (32 + lane) * 32 + kk);
            ADD2(ACC2, ACC2, v);
        }
        float bLo, bHi; UPK2(bLo, bHi, ACC2);
        acc2 = bLo + bHi;
    }
    // Fold overflow bins: 36 -> 0, 37 -> 1 (held by lanes 4, 5 in acc2).
    float b36 = __shfl_sync(FULL, acc2, 4);
    float b37 = __shfl_sync(FULL, acc2, 5);
    if (lane == 0) acc += b36;
    if (lane == 1) acc += b37;

    float* red  = h + HSLOT;        // 36 raw bins
    float* red2 = red + 40;         // 36 smoothed bins
    red[lane] = acc;
    if (lane < 4) red[32 + lane] = acc2;
    __syncwarp();

    // Smooth all 36 bins with wrap-padded 5-tap kernel (immediate coefficients).
    float sv = SK0 * red[(lane + 34) % 36];
    sv = fmaf(SK1, red[(lane + 35) % 36], sv);
    sv = fmaf(SK2, red[lane],            sv);
    sv = fmaf(SK1, red[(lane + 1) % 36], sv);
    sv = fmaf(SK0, red[(lane + 2) % 36], sv);
    red2[lane] = sv;
    float sv2 = -1e30f;
    if (lane < 4) {
        int b = 32 + lane;
        sv2 = SK0 * red[(b + 34) % 36];
        sv2 = fmaf(SK1, red[(b + 35) % 36], sv2);
        sv2 = fmaf(SK2, red[b],             sv2);
        sv2 = fmaf(SK1, red[(b + 1) % 36],  sv2);
        sv2 = fmaf(SK0, red[(b + 2) % 36],  sv2);
        red2[b] = sv2;
    }
    __syncwarp();

    // Per-lane candidate: bin `lane`, optionally replaced by bin `32+lane`
    // (strict > keeps lowest-index-wins tie semantics since 32+lane > lane).
    float v = sv;
    int idx = lane;
    if (lane < 4 && sv2 > v) { v = sv2; idx = 32 + lane; }

    // Warp argmax (lowest index on ties, matching jnp.argmax).
#pragma unroll
    for (int off = 16; off; off >>= 1) {
        float v2 = __shfl_xor_sync(FULL, v, off);
        int   i2 = __shfl_xor_sync(FULL, idx, off);
        if (v2 > v || (v2 == v && i2 < idx)) { v = v2; idx = i2; }
    }

    if (lane == 0) {
        float left  = red2[(idx + 35) % 36];
        float right = red2[(idx + 1) % 36];
        float denom = left + right - 2.0f * v;
        float c = 0.5f * (left - right) / denom;
        // angle = pi - (idx + c) * 2*pi/36   (the /HW scale cancels everywhere)
        float angle = 3.14159265358979f - ((float)idx + c) * 0.17453292519943295f;
        out[patch] = angle;
    }
}

// ---------------------------------------------------------------------------
extern "C" void kernel_launch(void* const* d_in, const int* in_sizes, int n_in,
                              void* d_out, int out_size) {
    const float* patch = (const float*)d_in[0];
    float* out = (float*)d_out;
    int n_patches = in_sizes[0] / (PATCH * PATCH);   // 32768

    int blocks = n_patches / WARPS_PER_BLOCK;        // 8192
    patch_orient_kernel<<<blocks, WARPS_PER_BLOCK * 32>>>(patch, out);
}

// round 14
// speedup vs baseline: 1.0721x; 1.0551x over previous
#include <cuda_runtime.h>
#include <math.h>

#define NUM_BINS 36
#define WARPS_PER_BLOCK 4
#define PATCH 32
#define HBINS 38                   // 36 + 2 overflow bins (36->0, 37->1)
#define HSLOT (HBINS * 32)         // 1216 floats: hist[38][32]
#define WSTRIDE 1296               // hist + raw(40) + smoothed(40)

// Discrete Gaussian smoothing kernel (sigma=1.6, ksize=5), analytically:
// k_j = I_|j|(2.56) / (I_0 + 2 I_1 + 2 I_2)   (the e^{-t} factor cancels).
#define SK0 0.11906250f
#define SK1 0.23112358f
#define SK2 0.29962786f

// Gaussian weights g[r] = exp(-(r-15.5)^2 * 36/2048), r = 0..31 (analytic).
#define GSUMF 13.3331107f
__host__ __device__ constexpr float GWv(int r) {
    constexpr float t[16] = {
        0.01465249f, 0.02482757f, 0.04061518f, 0.06414674f,
        0.09781210f, 0.14399383f, 0.20465581f, 0.28082614f,
        0.37203420f, 0.47583903f, 0.58758270f, 0.70050263f,
        0.80627370f, 0.89595700f, 0.96122114f, 0.99561511f };
    return (r < 16) ? t[r] : t[31 - r];
}

typedef unsigned long long u64;

// Packed f32x2 ops (sm_103a FFMA2/FADD2/FMUL2 — only reachable via PTX).
#define FMA2(d, a, b, c) asm("fma.rn.f32x2 %0, %1, %2, %3;" : "=l"(d) : "l"(a), "l"(b), "l"(c))
#define MUL2(d, a, b)    asm("mul.rn.f32x2 %0, %1, %2;"     : "=l"(d) : "l"(a), "l"(b))
#define ADD2(d, a, b)    asm("add.rn.f32x2 %0, %1, %2;"     : "=l"(d) : "l"(a), "l"(b))
#define SUB2(d, a, b)    asm("sub.rn.f32x2 %0, %1, %2;"     : "=l"(d) : "l"(a), "l"(b))
#define UPK2(l0, h0, s)  asm("mov.b64 {%0, %1}, %2;"        : "=f"(l0), "=f"(h0) : "l"(s))

__device__ __forceinline__ u64 pack2(float a, float b) {
    u64 r; asm("mov.b64 %0, {%1, %2};" : "=l"(r) : "f"(a), "f"(b)); return r;
}

__device__ __forceinline__ float sqrt_approx(float x) {
    float r; asm("sqrt.approx.f32 %0, %1;" : "=f"(r) : "f"(x)); return r;
}

// ---------------------------------------------------------------------------
// One warp per patch. Two rows per iteration, all packable math in f32x2.
// Conv-order swap: shuffle the RAW pixel row once (shfl.up/down immediate,
// whose edge clamp IS the reference's replicate padding), horizontal combos
// in-register, vertical taps via rolling window. Scalar binning tail.
// ---------------------------------------------------------------------------
__global__ void __launch_bounds__(WARPS_PER_BLOCK * 32, 9)
patch_orient_kernel(const float* __restrict__ in, float* __restrict__ out) {
    __shared__ __align__(16) float hist[WARPS_PER_BLOCK * WSTRIDE];

    const unsigned FULL = 0xffffffffu;
    int tid  = threadIdx.x;
    int warp = tid >> 5;
    int lane = tid & 31;
    int patch = blockIdx.x * WARPS_PER_BLOCK + warp;

    // Per-lane column weight factor, fully folded:
    // kk = g_lane * 0.125 / GSUM^2  (row literal g_r multiplies in the loop).
    float xg = (float)lane - 15.5f;
    float g  = expf(-xg * xg * 0.017578125f);
    const float kkf = g * (0.125f / (GSUMF * GSUMF));

    // Packed constants (register pairs; FFMA2 cannot read cbank).
    // Poly coefficients: ~1ulp atan minimax PRE-SCALED by 18/pi.
    const u64 CTWO  = pack2(2.0f, 2.0f);
    const u64 CEPS8 = pack2(8e-8f, 8e-8f);
    const u64 CEPS2 = pack2(6.4e-7f, 6.4e-7f);
    const u64 CK  = pack2(5.7295779513082321f, 5.7295779513082321f); // 18/pi
    const u64 CC7 = pack2( 0.0161782457f,  0.0161782457f);
    const u64 CC6 = pack2(-0.0914263090f, -0.0914263090f);
    const u64 CC5 = pack2( 0.2435356455f,  0.2435356455f);
    const u64 CC4 = pack2(-0.4290686200f, -0.4290686200f);
    const u64 CC3 = pack2( 0.6093287740f,  0.6093287740f);
    const u64 CC2 = pack2(-0.8137568480f, -0.8137568480f);
    const u64 CC1 = pack2( 1.1454970880f,  1.1454970880f);
    const u64 CC0 = pack2(-1.9098460550f, -1.9098460550f);

    float* h = hist + warp * WSTRIDE;
#pragma unroll
    for (int b = 0; b < HBINS / 2; b++)                   // packed zero-init
        *(u64*)(h + b * 64 + lane * 2) = 0ull;
    __syncwarp();   // init writes cross lane columns -> publish first

    const float* src = in + (size_t)patch * (PATCH * PATCH) + lane;
    float p[PATCH];
#pragma unroll
    for (int r = 0; r < 6; r++) p[r] = src[r * PATCH];   // prefetch prologue

    // Base pointer pre-biased by -36 rows so addr = base + i0raw*128.
    float* hl = h + lane - 36 * 32;

    // Rolling window: CARR = (hd/hs of rows r0-1, r0). Row -1 clamps to row 0.
    // shfl.up/down delta=1: out-of-range lanes keep own value = edge clamp.
    float pl0 = __shfl_up_sync(FULL, p[0], 1);
    float pr0 = __shfl_down_sync(FULL, p[0], 1);
    float hd0 = pr0 - pl0;
    float hs0 = fmaf(2.0f, p[0], pl0 + pr0);
    u64 CARR_HD = pack2(hd0, hd0);
    u64 CARR_HS = pack2(hs0, hs0);

#pragma unroll
    for (int i = 0; i < PATCH / 2; i++) {
        const int r0 = 2 * i, r1 = 2 * i + 1;
        const int f1 = (r1 + 1 < PATCH) ? r1 + 1 : PATCH - 1;  // row 32 -> 31

        // Prefetch ring: rows r0+6, r0+7 (guards are compile-time).
        if (r0 + 6 < PATCH) p[r0 + 6] = src[(r0 + 6) * PATCH];
        if (r0 + 7 < PATCH) p[r0 + 7] = src[(r0 + 7) * PATCH];

        // Fresh rows (r1, f1): ONE packed pixel shuffle pair (edge-clamping).
        u64 P  = pack2(p[r1], p[f1]);
        u64 PL = __shfl_up_sync(FULL, P, 1);
        u64 PR = __shfl_down_sync(FULL, P, 1);

        u64 FHD; SUB2(FHD, PR, PL);              // (hd[r1], hd[r1+1])
        u64 TT;  ADD2(TT, PL, PR);
        u64 FHS; FMA2(FHS, P, CTWO, TT);         // (hs[r1], hs[r1+1])

        // GX = CARR_HD + 2*MID + FHD, MID = (hd[r0], hd[r1]).
        float chd_lo, chd_hi; UPK2(chd_lo, chd_hi, CARR_HD);
        float fhd_lo, fhd_hi; UPK2(fhd_lo, fhd_hi, FHD);
        u64 MID = pack2(chd_hi, fhd_lo);
        u64 TG;  ADD2(TG, CARR_HD, FHD);
        u64 GX;  FMA2(GX, MID, CTWO, TG);        // 8*gx rows (r0, r1)
        u64 GXE; ADD2(GXE, GX, CEPS8);           // + 8e-8 (ref eps, scaled)
        u64 GY;  SUB2(GY, FHS, CARR_HS);         // 8*gy = hs[r+1]-hs[r-1]
        CARR_HD = FHD;
        CARR_HS = FHS;

        u64 M2;  FMA2(M2, GY, GY, CEPS2);
        FMA2(M2, GXE, GXE, M2);

        // Scalar magnitude path: FMUL + FMUL-immediate (row weight literal).
        float m20, m21; UPK2(m20, m21, M2);
        float mag0 = (sqrt_approx(m20) * kkf) * GWv(r0);
        float mag1 = (sqrt_approx(m21) * kkf) * GWv(r1);

        float gx0, gx1, gy0, gy1;
        UPK2(gx0, gx1, GXE);
        UPK2(gy0, gy1, GY);

        // atan2 front (scalar: MUFU + min/max with |.| operand modifiers).
        float mx0 = fmaxf(fabsf(gx0), fabsf(gy0));
        float mn0 = fminf(fabsf(gx0), fabsf(gy0));
        float t0  = __fdividef(mn0, mx0);
        float mx1 = fmaxf(fabsf(gx1), fabsf(gy1));
        float mn1 = fminf(fabsf(gx1), fabsf(gy1));
        float t1  = __fdividef(mn1, mx1);

        // Packed pre-scaled atan poly: u = (18/pi)*atan(t), u in [0, 4.5].
        u64 T = pack2(t0, t1);
        u64 S;  MUL2(S, T, T);
        u64 Q;  FMA2(Q, CC7, S, CC6);
        FMA2(Q, Q, S, CC5);
        FMA2(Q, Q, S, CC4);
        FMA2(Q, Q, S, CC3);
        FMA2(Q, Q, S, CC2);
        FMA2(Q, Q, S, CC1);
        FMA2(Q, Q, S, CC0);
        FMA2(Q, Q, S, CK);                       // Q = 18/pi + s*P(s)
        u64 U;  MUL2(U, Q, T);                   // u = Q*t
        float u0, u1; UPK2(u0, u1, U);

        // Octant fixups in bin units (pi/2 -> 9, pi -> 18). u stays in [0,18].
        if (fabsf(gy0) > fabsf(gx0)) u0 = 9.0f  - u0;
        if (gx0 < 0.0f)              u0 = 18.0f - u0;
        float v0 = copysignf(u0, gy0);
        if (fabsf(gy1) > fabsf(gx1)) u1 = 9.0f  - u1;
        if (gx1 < 0.0f)              u1 = 18.0f - u1;
        float v1 = copysignf(u1, gy1);

        // o = v + 54 is in [36, 72] by construction (no guard needed).
        float o0 = v0 + 54.0f;
        float fo0 = floorf(o0);
        float wo10 = o0 - fo0;
        int i00 = (int)fo0;                     // in [36, 72]
        float w1v0 = wo10 * mag0;
        float w0v0 = mag0 - w1v0;
        float* q0p = hl + i00 * 32;             // bank == lane: conflict-free
        q0p[0]  += w0v0;
        q0p[32] += w1v0;

        float o1 = v1 + 54.0f;
        float fo1 = floorf(o1);
        float wo11 = o1 - fo1;
        int i01 = (int)fo1;
        float w1v1 = wo11 * mag1;
        float w0v1 = mag1 - w1v1;
        float* q1p = hl + i01 * 32;
        q1p[0]  += w0v1;
        q1p[32] += w1v1;
    }
    __syncwarp();

    // Packed reduce: 38 bins x 32 lane-slots as 16 u64 per bin, lane-rotated.
    // Lane l sums bin l; lanes 0-5 also bins 32+l.
    u64 ACC = 0ull;
#pragma unroll
    for (int k = 0; k < 16; k++) {
        int kk = ((k + lane) & 15) * 2;          // rotate -> spread banks
        u64 v = *(const u64*)(h + lane * 32 + kk);
        ADD2(ACC, ACC, v);
    }
    float aLo, aHi; UPK2(aLo, aHi, ACC);
    float acc = aLo + aHi;

    float acc2 = 0.0f;
    if (lane < 6) {
        u64 ACC2 = 0ull;
#pragma unroll
        for (int k = 0; k < 16; k++) {
            int kk = ((k + lane) & 15) * 2;
            u64 v = *(const u64*)(h + (32 + lane) * 32 + kk);
            ADD2(ACC2, ACC2, v);
        }
        float bLo, bHi; UPK2(bLo, bHi, ACC2);
        acc2 = bLo + bHi;
    }
    // Fold overflow bins: 36 -> 0, 37 -> 1 (held by lanes 4, 5 in acc2).
    float b36 = __shfl_sync(FULL, acc2, 4);
    float b37 = __shfl_sync(FULL, acc2, 5);
    if (lane == 0) acc += b36;
    if (lane == 1) acc += b37;

    float* red  = h + HSLOT;        // 36 raw bins
    float* red2 = red + 40;         // 36 smoothed bins
    red[lane] = acc;
    if (lane < 4) red[32 + lane] = acc2;
    __syncwarp();

    // Smooth all 36 bins with wrap-padded 5-tap kernel (immediate coefficients).
    float sv = SK0 * red[(lane + 34) % 36];
    sv = fmaf(SK1, red[(lane + 35) % 36], sv);
    sv = fmaf(SK2, red[lane],            sv);
    sv = fmaf(SK1, red[(lane + 1) % 36], sv);
    sv = fmaf(SK0, red[(lane + 2) % 36], sv);
    red2[lane] = sv;
    float sv2 = -1e30f;
    if (lane < 4) {
        int b = 32 + lane;
        sv2 = SK0 * red[(b + 34) % 36];
        sv2 = fmaf(SK1, red[(b + 35) % 36], sv2);
        sv2 = fmaf(SK2, red[b],             sv2);
        sv2 = fmaf(SK1, red[(b + 1) % 36],  sv2);
        sv2 = fmaf(SK0, red[(b + 2) % 36],  sv2);
        red2[b] = sv2;
    }
    __syncwarp();

    // Per-lane candidate: bin `lane`, optionally replaced by bin `32+lane`
    // (strict > keeps lowest-index-wins tie semantics since 32+lane > lane).
    float v = sv;
    int idx = lane;
    if (lane < 4 && sv2 > v) { v = sv2; idx = 32 + lane; }

    // Warp argmax (lowest index on ties, matching jnp.argmax).
#pragma unroll
    for (int off = 16; off; off >>= 1) {
        float v2 = __shfl_xor_sync(FULL, v, off);
        int   i2 = __shfl_xor_sync(FULL, idx, off);
        if (v2 > v || (v2 == v && i2 < idx)) { v = v2; idx = i2; }
    }

    if (lane == 0) {
        float left  = red2[(idx + 35) % 36];
        float right = red2[(idx + 1) % 36];
        float denom = left + right - 2.0f * v;
        float c = 0.5f * (left - right) / denom;
        // angle = pi - (idx + c) * 2*pi/36   (the /HW scale cancels everywhere)
        float angle = 3.14159265358979f - ((float)idx + c) * 0.17453292519943295f;
        out[patch] = angle;
    }
}

// ---------------------------------------------------------------------------
extern "C" void kernel_launch(void* const* d_in, const int* in_sizes, int n_in,
                              void* d_out, int out_size) {
    const float* patch = (const float*)d_in[0];
    float* out = (float*)d_out;
    int n_patches = in_sizes[0] / (PATCH * PATCH);   // 32768

    int blocks = n_patches / WARPS_PER_BLOCK;        // 8192
    patch_orient_kernel<<<blocks, WARPS_PER_BLOCK * 32>>>(patch, out);
}

// round 15
// speedup vs baseline: 1.0759x; 1.0036x over previous
#include <cuda_runtime.h>
#include <math.h>

#define NUM_BINS 36
#define WARPS_PER_BLOCK 4
#define PATCH 32
#define HBINS 38                   // 36 + 2 overflow bins (36->0, 37->1)
#define HSLOT (HBINS * 32)         // 1216 floats: hist[38][32]
#define WSTRIDE 1296               // hist + raw(40) + smoothed(40)

// Discrete Gaussian smoothing kernel (sigma=1.6, ksize=5), analytically:
// k_j = I_|j|(2.56) / (I_0 + 2 I_1 + 2 I_2)   (the e^{-t} factor cancels).
#define SK0 0.11906250f
#define SK1 0.23112358f
#define SK2 0.29962786f

// Gaussian weights g[r] = exp(-(r-15.5)^2 * 36/2048), r = 0..31 (analytic).
// GSUMF = sum_r g[r]; absolute weight scale cancels in argmax/parabola.
#define GSUMF 13.3331107f
__host__ __device__ constexpr float GWv(int r) {
    constexpr float t[16] = {
        0.01465249f, 0.02482757f, 0.04061518f, 0.06414674f,
        0.09781210f, 0.14399383f, 0.20465581f, 0.28082614f,
        0.37203420f, 0.47583903f, 0.58758270f, 0.70050263f,
        0.80627370f, 0.89595700f, 0.96122114f, 0.99561511f };
    return (r < 16) ? t[r] : t[31 - r];
}

typedef unsigned long long u64;

// Packed f32x2 ops (sm_103a FFMA2/FADD2/FMUL2 — only reachable via PTX).
#define FMA2(d, a, b, c) asm("fma.rn.f32x2 %0, %1, %2, %3;" : "=l"(d) : "l"(a), "l"(b), "l"(c))
#define MUL2(d, a, b)    asm("mul.rn.f32x2 %0, %1, %2;"     : "=l"(d) : "l"(a), "l"(b))
#define ADD2(d, a, b)    asm("add.rn.f32x2 %0, %1, %2;"     : "=l"(d) : "l"(a), "l"(b))
#define SUB2(d, a, b)    asm("sub.rn.f32x2 %0, %1, %2;"     : "=l"(d) : "l"(a), "l"(b))
#define UPK2(l0, h0, s)  asm("mov.b64 {%0, %1}, %2;"        : "=f"(l0), "=f"(h0) : "l"(s))

__device__ __forceinline__ u64 pack2(float a, float b) {
    u64 r; asm("mov.b64 %0, {%1, %2};" : "=l"(r) : "f"(a), "f"(b)); return r;
}

__device__ __forceinline__ float sqrt_approx(float x) {
    float r; asm("sqrt.approx.f32 %0, %1;" : "=f"(r) : "f"(x)); return r;
}

// ---------------------------------------------------------------------------
// One warp per patch. Two rows per iteration, all packable math in f32x2.
// Conv-order swap: shuffle the RAW pixel row once (shfl.up/down immediate,
// whose edge clamp IS the reference's replicate padding), horizontal combos
// in-register, vertical taps via rolling window. Scalar binning tail.
// ---------------------------------------------------------------------------
__global__ void __launch_bounds__(WARPS_PER_BLOCK * 32, 9)
patch_orient_kernel(const float* __restrict__ in, float* __restrict__ out) {
    __shared__ __align__(16) float hist[WARPS_PER_BLOCK * WSTRIDE];

    const unsigned FULL = 0xffffffffu;
    int tid  = threadIdx.x;
    int warp = tid >> 5;
    int lane = tid & 31;
    int patch = blockIdx.x * WARPS_PER_BLOCK + warp;

    // Per-lane column weight factor, fully folded with the Sobel 1/8 and the
    // literal normalization (uniform scale cancels downstream):
    // kk = exp(-x^2/(2*sigma^2)) * 0.125 / GSUM^2,  1/(2 sigma^2) = 36/2048.
    float xg = (float)lane - 15.5f;
    const float kkf = expf(-xg * xg * 0.017578125f) * (0.125f / (GSUMF * GSUMF));

    // Packed constants (register pairs; FFMA2 cannot read cbank).
    // Poly coefficients: ~1ulp atan minimax PRE-SCALED by 18/pi.
    const u64 CTWO  = pack2(2.0f, 2.0f);
    const u64 CEPS8 = pack2(8e-8f, 8e-8f);
    const u64 CEPS2 = pack2(6.4e-7f, 6.4e-7f);
    const u64 CK  = pack2(5.7295779513082321f, 5.7295779513082321f); // 18/pi
    const u64 CC7 = pack2( 0.0161782457f,  0.0161782457f);
    const u64 CC6 = pack2(-0.0914263090f, -0.0914263090f);
    const u64 CC5 = pack2( 0.2435356455f,  0.2435356455f);
    const u64 CC4 = pack2(-0.4290686200f, -0.4290686200f);
    const u64 CC3 = pack2( 0.6093287740f,  0.6093287740f);
    const u64 CC2 = pack2(-0.8137568480f, -0.8137568480f);
    const u64 CC1 = pack2( 1.1454970880f,  1.1454970880f);
    const u64 CC0 = pack2(-1.9098460550f, -1.9098460550f);

    float* h = hist + warp * WSTRIDE;
#pragma unroll
    for (int b = 0; b < HBINS / 2; b++)                   // packed zero-init
        *(u64*)(h + b * 64 + lane * 2) = 0ull;
    __syncwarp();   // init writes cross lane columns -> publish first

    const float* src = in + (size_t)patch * (PATCH * PATCH) + lane;
    float p[PATCH];
#pragma unroll
    for (int r = 0; r < 6; r++) p[r] = src[r * PATCH];   // prefetch prologue

    // Base pointer pre-biased by -36 rows so addr = base + i0raw*128.
    float* hl = h + lane - 36 * 32;

    // Rolling window: CARR = (hd/hs of rows r0-1, r0). Row -1 clamps to row 0.
    // shfl.up/down delta=1: out-of-range lanes keep own value = edge clamp.
    float pl0 = __shfl_up_sync(FULL, p[0], 1);
    float pr0 = __shfl_down_sync(FULL, p[0], 1);
    float hd0 = pr0 - pl0;
    float hs0 = fmaf(2.0f, p[0], pl0 + pr0);
    u64 CARR_HD = pack2(hd0, hd0);
    u64 CARR_HS = pack2(hs0, hs0);

#pragma unroll
    for (int i = 0; i < PATCH / 2; i++) {
        const int r0 = 2 * i, r1 = 2 * i + 1;
        const int f1 = (r1 + 1 < PATCH) ? r1 + 1 : PATCH - 1;  // row 32 -> 31

        // Prefetch ring: rows r0+6, r0+7 (guards are compile-time).
        if (r0 + 6 < PATCH) p[r0 + 6] = src[(r0 + 6) * PATCH];
        if (r0 + 7 < PATCH) p[r0 + 7] = src[(r0 + 7) * PATCH];

        // Fresh rows (r1, f1): ONE packed pixel shuffle pair (edge-clamping).
        u64 P  = pack2(p[r1], p[f1]);
        u64 PL = __shfl_up_sync(FULL, P, 1);
        u64 PR = __shfl_down_sync(FULL, P, 1);

        u64 FHD; SUB2(FHD, PR, PL);              // (hd[r1], hd[r1+1])
        u64 TT;  ADD2(TT, PL, PR);
        u64 FHS; FMA2(FHS, P, CTWO, TT);         // (hs[r1], hs[r1+1])

        // GX = CARR_HD + 2*MID + FHD, MID = (hd[r0], hd[r1]).
        float chd_lo, chd_hi; UPK2(chd_lo, chd_hi, CARR_HD);
        float fhd_lo, fhd_hi; UPK2(fhd_lo, fhd_hi, FHD);
        u64 MID = pack2(chd_hi, fhd_lo);
        u64 TG;  ADD2(TG, CARR_HD, FHD);
        u64 GX;  FMA2(GX, MID, CTWO, TG);        // 8*gx rows (r0, r1)
        u64 GXE; ADD2(GXE, GX, CEPS8);           // + 8e-8 (ref eps, scaled)
        u64 GY;  SUB2(GY, FHS, CARR_HS);         // 8*gy = hs[r+1]-hs[r-1]
        CARR_HD = FHD;
        CARR_HS = FHS;

        u64 M2;  FMA2(M2, GY, GY, CEPS2);
        FMA2(M2, GXE, GXE, M2);

        // Scalar magnitude path: FMUL + FMUL-immediate (row weight literal).
        float m20, m21; UPK2(m20, m21, M2);
        float mag0 = (sqrt_approx(m20) * kkf) * GWv(r0);
        float mag1 = (sqrt_approx(m21) * kkf) * GWv(r1);

        float gx0, gx1, gy0, gy1;
        UPK2(gx0, gx1, GXE);
        UPK2(gy0, gy1, GY);

        // atan2 front (scalar: MUFU + min/max with |.| operand modifiers).
        float mx0 = fmaxf(fabsf(gx0), fabsf(gy0));
        float mn0 = fminf(fabsf(gx0), fabsf(gy0));
        float t0  = __fdividef(mn0, mx0);
        float mx1 = fmaxf(fabsf(gx1), fabsf(gy1));
        float mn1 = fminf(fabsf(gx1), fabsf(gy1));
        float t1  = __fdividef(mn1, mx1);

        // Packed pre-scaled atan poly: u = (18/pi)*atan(t), u in [0, 4.5].
        u64 T = pack2(t0, t1);
        u64 S;  MUL2(S, T, T);
        u64 Q;  FMA2(Q, CC7, S, CC6);
        FMA2(Q, Q, S, CC5);
        FMA2(Q, Q, S, CC4);
        FMA2(Q, Q, S, CC3);
        FMA2(Q, Q, S, CC2);
        FMA2(Q, Q, S, CC1);
        FMA2(Q, Q, S, CC0);
        FMA2(Q, Q, S, CK);                       // Q = 18/pi + s*P(s)
        u64 U;  MUL2(U, Q, T);                   // u = Q*t
        float u0, u1; UPK2(u0, u1, U);

        // Octant fixups in bin units (pi/2 -> 9, pi -> 18). u stays in [0,18].
        if (fabsf(gy0) > fabsf(gx0)) u0 = 9.0f  - u0;
        if (gx0 < 0.0f)              u0 = 18.0f - u0;
        float v0 = copysignf(u0, gy0);
        if (fabsf(gy1) > fabsf(gx1)) u1 = 9.0f  - u1;
        if (gx1 < 0.0f)              u1 = 18.0f - u1;
        float v1 = copysignf(u1, gy1);

        // o = v + 54 is in [36, 72] by construction (no guard needed).
        float o0 = v0 + 54.0f;
        float fo0 = floorf(o0);
        float wo10 = o0 - fo0;
        int i00 = (int)fo0;                     // in [36, 72]
        float w1v0 = wo10 * mag0;
        float w0v0 = mag0 - w1v0;
        float* q0p = hl + i00 * 32;             // bank == lane: conflict-free
        q0p[0]  += w0v0;
        q0p[32] += w1v0;

        float o1 = v1 + 54.0f;
        float fo1 = floorf(o1);
        float wo11 = o1 - fo1;
        int i01 = (int)fo1;
        float w1v1 = wo11 * mag1;
        float w0v1 = mag1 - w1v1;
        float* q1p = hl + i01 * 32;
        q1p[0]  += w0v1;
        q1p[32] += w1v1;
    }
    __syncwarp();

    // Packed reduce: 38 bins x 32 lane-slots as 16 u64 per bin, lane-rotated.
    // Lane l sums bin l; lanes 0-5 also bins 32+l.
    u64 ACC = 0ull;
#pragma unroll
    for (int k = 0; k < 16; k++) {
        int kk = ((k + lane) & 15) * 2;          // rotate -> spread banks
        u64 v = *(const u64*)(h + lane * 32 + kk);
        ADD2(ACC, ACC, v);
    }
    float aLo, aHi; UPK2(aLo, aHi, ACC);
    float acc = aLo + aHi;

    float acc2 = 0.0f;
    if (lane < 6) {
        u64 ACC2 = 0ull;
#pragma unroll
        for (int k = 0; k < 16; k++) {
            int kk = ((k + lane) & 15) * 2;
            u64 v = *(const u64*)(h + (32 + lane) * 32 + kk);
            ADD2(ACC2, ACC2, v);
        }
        float bLo, bHi; UPK2(bLo, bHi, ACC2);
        acc2 = bLo + bHi;
    }
    // Fold overflow bins: 36 -> 0, 37 -> 1 (held by lanes 4, 5 in acc2).
    float b36 = __shfl_sync(FULL, acc2, 4);
    float b37 = __shfl_sync(FULL, acc2, 5);
    if (lane == 0) acc += b36;
    if (lane == 1) acc += b37;

    float* red  = h + HSLOT;        // 36 raw bins
    float* red2 = red + 40;         // 36 smoothed bins
    red[lane] = acc;
    if (lane < 4) red[32 + lane] = acc2;
    __syncwarp();

    // Smooth all 36 bins with wrap-padded 5-tap kernel (immediate coefficients).
    float sv = SK0 * red[(lane + 34) % 36];
    sv = fmaf(SK1, red[(lane + 35) % 36], sv);
    sv = fmaf(SK2, red[lane],            sv);
    sv = fmaf(SK1, red[(lane + 1) % 36], sv);
    sv = fmaf(SK0, red[(lane + 2) % 36], sv);
    red2[lane] = sv;
    float sv2 = -1e30f;
    if (lane < 4) {
        int b = 32 + lane;
        sv2 = SK0 * red[(b + 34) % 36];
        sv2 = fmaf(SK1, red[(b + 35) % 36], sv2);
        sv2 = fmaf(SK2, red[b],             sv2);
        sv2 = fmaf(SK1, red[(b + 1) % 36],  sv2);
        sv2 = fmaf(SK0, red[(b + 2) % 36],  sv2);
        red2[b] = sv2;
    }
    __syncwarp();

    // Per-lane candidate: bin `lane`, optionally replaced by bin `32+lane`
    // (strict > keeps lowest-index-wins tie semantics since 32+lane > lane).
    float v = sv;
    int idx = lane;
    if (lane < 4 && sv2 > v) { v = sv2; idx = 32 + lane; }

    // Warp argmax (lowest index on ties, matching jnp.argmax).
#pragma unroll
    for (int off = 16; off; off >>= 1) {
        float v2 = __shfl_xor_sync(FULL, v, off);
        int   i2 = __shfl_xor_sync(FULL, idx, off);
        if (v2 > v || (v2 == v && i2 < idx)) { v = v2; idx = i2; }
    }

    if (lane == 0) {
        float left  = red2[(idx + 35) % 36];
        float right = red2[(idx + 1) % 36];
        float denom = left + right - 2.0f * v;
        float c = 0.5f * (left - right) / denom;
        // angle = pi - (idx + c) * 2*pi/36   (the /HW scale cancels everywhere)
        float angle = 3.14159265358979f - ((float)idx + c) * 0.17453292519943295f;
        out[patch] = angle;
    }
}

// ---------------------------------------------------------------------------
extern "C" void kernel_launch(void* const* d_in, const int* in_sizes, int n_in,
                              void* d_out, int out_size) {
    const float* patch = (const float*)d_in[0];
    float* out = (float*)d_out;
    int n_patches = in_sizes[0] / (PATCH * PATCH);   // 32768

    int blocks = n_patches / WARPS_PER_BLOCK;        // 8192
    patch_orient_kernel<<<blocks, WARPS_PER_BLOCK * 32>>>(patch, out);
}